// round 12
// baseline (speedup 1.0000x reference)
#include <cuda_runtime.h>

// LSTM2: 2-layer LSTM, B=1024, T=1024, H=64, input dim 1, output 1/step.
// Persistent-RNN with WARP-SPECIALIZED LAYER PIPELINE:
//   128 CTAs x 384 threads, 8 batch rows per CTA.
//   Group A (warps 0-3, 128 thr): layer-1 producer. At interval k computes
//     h1(k) from x(k), h1(k-1). Thread = (unit n, row-half rh): full 64-k
//     dots for 4 gates x 4 rows, NO shuffles, cell state c1[4] in regs.
//   Group B (warps 4-11, 256 thr): layer-2 consumer + output. At interval k
//     computes h2(k-1) from h1(k-1), h2(k-2) (R8 mapping: thread=(n,kq),
//     4 gates x 8 rows x 16k, 2-level shfl butterfly, rows {kq,kq+4}),
//     and the w_lin output for step k-2.
// ONE __syncthreads per interval; h1/h2 double buffers carry the pipeline.
// Layer-1 epilogue overlaps layer-2 compute and vice versa; 3 warps/SMSP.

namespace {

constexpr int T_LEN = 1024;
constexpr int RPC   = 8;             // batch rows per CTA
constexpr int NTH   = 384;           // 4 A-warps + 8 B-warps
constexpr int GRID  = 1024 / RPC;    // 128

constexpr int WP = 68;               // weight row pitch (floats)
constexpr int HP = 72;               // h row pitch (floats)
constexpr int HB = RPC * HP;         // 576 floats per h buffer

constexpr int SMEM_FLOATS = 3 * 256 * WP + 64 + 4 * HB + 16;
constexpr int SMEM_BYTES  = SMEM_FLOATS * 4;   // 218432 B

typedef unsigned long long u64;

__device__ __forceinline__ u64 fma2(u64 a, u64 b, u64 c) {
    u64 d;
    asm("fma.rn.f32x2 %0, %1, %2, %3;" : "=l"(d) : "l"(a), "l"(b), "l"(c));
    return d;
}
__device__ __forceinline__ float red2(u64 a) {
    return __uint_as_float((unsigned)a) + __uint_as_float((unsigned)(a >> 32));
}
__device__ __forceinline__ float tanh_f(float v) {
    float r;
    asm("tanh.approx.f32 %0, %1;" : "=f"(r) : "f"(v));
    return r;
}
__device__ __forceinline__ float sigm(float v) {
    return fmaf(tanh_f(0.5f * v), 0.5f, 0.5f);
}
__device__ __forceinline__ ulonglong2 ld2(const float* p) {
    return *(const ulonglong2*)p;
}

} // namespace

__global__ void __launch_bounds__(NTH, 1)
lstm2_kernel(const float* __restrict__ x,
             const float* __restrict__ w_ih1, const float* __restrict__ w_hh1,
             const float* __restrict__ b_ih1, const float* __restrict__ b_hh1,
             const float* __restrict__ w_ih2, const float* __restrict__ w_hh2,
             const float* __restrict__ b_ih2, const float* __restrict__ b_hh2,
             const float* __restrict__ w_lin, const float* __restrict__ b_lin,
             float* __restrict__ out)
{
    extern __shared__ float sm[];
    float* sWh1 = sm;                    // [256][68]  layer1 w_hh
    float* sWi2 = sWh1 + 256 * WP;       // [256][68]  layer2 w_ih
    float* sWh2 = sWi2 + 256 * WP;       // [256][68]  layer2 w_hh
    float* sWl  = sWh2 + 256 * WP;       // [64]
    float* sH1  = sWl + 64;              // [2][8][72] h1 ring
    float* sH2  = sH1 + 2 * HB;          // [2][8][72] h2 ring
    float* sX   = sH2 + 2 * HB;          // [2][8]     x staging

    const int tid = threadIdx.x;
    const int rowbase = blockIdx.x * RPC;

    // ---- init: weights to padded SMEM, zero h buffers, stage x(0) ----
    for (int i = tid; i < 256 * 64; i += NTH) {
        int j = i >> 6, k = i & 63;
        int off = j * WP + k;
        sWh1[off] = w_hh1[i];
        sWi2[off] = w_ih2[i];
        sWh2[off] = w_hh2[i];
    }
    if (tid < 64) sWl[tid] = w_lin[tid];
    for (int i = tid; i < 4 * HB; i += NTH) sH1[i] = 0.f;   // zeros h1 AND h2
    if (tid < 16) sX[tid] = 0.f;
    if (tid < RPC) sX[tid] = x[(rowbase + tid) * T_LEN];    // x(0) -> stage 0
    __syncthreads();

    const int wid = tid >> 5, lid = tid & 31;
    const bool isA = (wid < 4);

    // group-specific thread mapping
    const int rh   = (tid >> 6) & 1;            // A: row-half (rows 4rh..4rh+3)
    const int bwid = wid - 4;                   // B: warp index 0..7
    const int kq   = lid >> 3;                  // B: k-quarter 0..3
    const int n    = isA ? (tid & 63) : ((bwid << 3) | (lid & 7));
    const int hi2  = kq & 2, hi1 = kq & 1;
    const int rAq  = kq, rBq = kq + 4;          // B: rows this lane finalizes

    // per-thread constants (group-dependent)
    float gb[4], gwx[4];
    #pragma unroll
    for (int g = 0; g < 4; ++g) {
        int idx = n + 64 * g;
        if (isA) { gb[g] = b_ih1[idx] + b_hh1[idx]; gwx[g] = w_ih1[idx]; }
        else     { gb[g] = b_ih2[idx] + b_hh2[idx]; gwx[g] = 0.f; }
    }
    const float blin = b_lin[0];

    // weight pointers
    const float* WA = sWh1 + n * WP;                 // A: gate g at +g*64*WP
    const float* Ub = sWi2 + n * WP + kq * 16;       // B: layer2 w_ih
    const float* Vb = sWh2 + n * WP + kq * 16;       // B: layer2 w_hh

    // persistent cell state
    float c1[4] = {0.f, 0.f, 0.f, 0.f};   // A: rows 4rh..4rh+3
    float c2a = 0.f, c2b = 0.f;            // B: rows kq, kq+4

    for (int k = 0; k < T_LEN + 2; ++k) {
        if (isA) {
            // ======== group A: layer 1, step k ========
            if (k < T_LEN) {
                float xn = 0.f;
                if (tid < RPC && k + 1 < T_LEN)
                    xn = x[(rowbase + tid) * T_LEN + (k + 1)];

                const float* hb = sH1 + ((k & 1) ^ 1) * HB + (rh * 4) * HP;
                u64 a[4][4] = {};
                #pragma unroll
                for (int i = 0; i < 16; ++i) {
                    const int io = i * 4;
                    ulonglong2 wv[4], hv[4];
                    #pragma unroll
                    for (int g = 0; g < 4; ++g) wv[g] = ld2(WA + g * 64 * WP + io);
                    #pragma unroll
                    for (int r = 0; r < 4; ++r) hv[r] = ld2(hb + r * HP + io);
                    #pragma unroll
                    for (int g = 0; g < 4; ++g)
                        #pragma unroll
                        for (int r = 0; r < 4; ++r) {
                            a[g][r] = fma2(wv[g].x, hv[r].x, a[g][r]);
                            a[g][r] = fma2(wv[g].y, hv[r].y, a[g][r]);
                        }
                }
                const float* sxr = sX + (k & 1) * RPC + rh * 4;
                float* hw = sH1 + (k & 1) * HB + (rh * 4) * HP + n;
                #pragma unroll
                for (int j = 0; j < 4; ++j) {
                    float xs = sxr[j];
                    float ii = sigm(fmaf(gwx[0], xs, gb[0]) + red2(a[0][j]));
                    float ff = sigm(fmaf(gwx[1], xs, gb[1]) + red2(a[1][j]));
                    float gc = tanh_f(fmaf(gwx[2], xs, gb[2]) + red2(a[2][j]));
                    float oo = sigm(fmaf(gwx[3], xs, gb[3]) + red2(a[3][j]));
                    c1[j] = ff * c1[j] + ii * gc;
                    hw[j * HP] = oo * tanh_f(c1[j]);
                }
                if (tid < RPC && k + 1 < T_LEN)
                    sX[((k + 1) & 1) * RPC + tid] = xn;
            }
        } else {
            // ======== group B: output for step k-2 ========
            if (k >= 2) {
                const int ko = k - 2;
                const float* hr = sH2 + (ko & 1) * HB + bwid * HP;
                float v = hr[lid] * sWl[lid] + hr[lid + 32] * sWl[lid + 32];
                #pragma unroll
                for (int off = 16; off; off >>= 1)
                    v += __shfl_xor_sync(0xffffffffu, v, off);
                if (lid == 0) out[(rowbase + bwid) * T_LEN + ko] = v + blin;
            }
            // ======== group B: layer 2, step k-1 ========
            if (k >= 1 && k <= T_LEN) {
                const int s  = (k - 1) & 1;   // h1 read stage, h2 write stage
                const int sp = s ^ 1;         // h2 read stage (step k-2)
                u64 acc[4][8] = {};
                {
                    const float* hb = sH1 + s * HB + kq * 16;
                    #pragma unroll
                    for (int i = 0; i < 4; ++i) {
                        const int io = i * 4;
                        ulonglong2 wv[4];
                        #pragma unroll
                        for (int g = 0; g < 4; ++g) wv[g] = ld2(Ub + g * 64 * WP + io);
                        #pragma unroll
                        for (int r = 0; r < 8; ++r) {
                            ulonglong2 hv = ld2(hb + r * HP + io);
                            #pragma unroll
                            for (int g = 0; g < 4; ++g) {
                                acc[g][r] = fma2(wv[g].x, hv.x, acc[g][r]);
                                acc[g][r] = fma2(wv[g].y, hv.y, acc[g][r]);
                            }
                        }
                    }
                }
                {
                    const float* hb = sH2 + sp * HB + kq * 16;
                    #pragma unroll
                    for (int i = 0; i < 4; ++i) {
                        const int io = i * 4;
                        ulonglong2 wv[4];
                        #pragma unroll
                        for (int g = 0; g < 4; ++g) wv[g] = ld2(Vb + g * 64 * WP + io);
                        #pragma unroll
                        for (int r = 0; r < 8; ++r) {
                            ulonglong2 hv = ld2(hb + r * HP + io);
                            #pragma unroll
                            for (int g = 0; g < 4; ++g) {
                                acc[g][r] = fma2(wv[g].x, hv.x, acc[g][r]);
                                acc[g][r] = fma2(wv[g].y, hv.y, acc[g][r]);
                            }
                        }
                    }
                }
                // 2-level butterfly: lane kq ends with rows {kq, kq+4}
                float vA[4], vB[4];
                #pragma unroll
                for (int g = 0; g < 4; ++g) {
                    float p0 = red2(acc[g][0]), p1 = red2(acc[g][1]);
                    float p2 = red2(acc[g][2]), p3 = red2(acc[g][3]);
                    float p4 = red2(acc[g][4]), p5 = red2(acc[g][5]);
                    float p6 = red2(acc[g][6]), p7 = red2(acc[g][7]);
                    float va0 = (hi2 ? p2 : p0) + __shfl_xor_sync(~0u, hi2 ? p0 : p2, 16);
                    float va1 = (hi2 ? p3 : p1) + __shfl_xor_sync(~0u, hi2 ? p1 : p3, 16);
                    float va4 = (hi2 ? p6 : p4) + __shfl_xor_sync(~0u, hi2 ? p4 : p6, 16);
                    float va5 = (hi2 ? p7 : p5) + __shfl_xor_sync(~0u, hi2 ? p5 : p7, 16);
                    vA[g] = (hi1 ? va1 : va0) + __shfl_xor_sync(~0u, hi1 ? va0 : va1, 8);
                    vB[g] = (hi1 ? va5 : va4) + __shfl_xor_sync(~0u, hi1 ? va4 : va5, 8);
                }
                float ii = sigm(gb[0] + vA[0]);
                float ff = sigm(gb[1] + vA[1]);
                float gc = tanh_f(gb[2] + vA[2]);
                float oo = sigm(gb[3] + vA[3]);
                c2a = ff * c2a + ii * gc;
                sH2[s * HB + rAq * HP + n] = oo * tanh_f(c2a);
                ii = sigm(gb[0] + vB[0]);
                ff = sigm(gb[1] + vB[1]);
                gc = tanh_f(gb[2] + vB[2]);
                oo = sigm(gb[3] + vB[3]);
                c2b = ff * c2b + ii * gc;
                sH2[s * HB + rBq * HP + n] = oo * tanh_f(c2b);
            }
        }
        __syncthreads();   // interval handoff: h1(k), h2(k-1), x(k+1) published
    }
}

extern "C" void kernel_launch(void* const* d_in, const int* in_sizes, int n_in,
                              void* d_out, int out_size)
{
    const float* x     = (const float*)d_in[0];
    const float* w_ih1 = (const float*)d_in[1];
    const float* w_hh1 = (const float*)d_in[2];
    const float* b_ih1 = (const float*)d_in[3];
    const float* b_hh1 = (const float*)d_in[4];
    const float* w_ih2 = (const float*)d_in[5];
    const float* w_hh2 = (const float*)d_in[6];
    const float* b_ih2 = (const float*)d_in[7];
    const float* b_hh2 = (const float*)d_in[8];
    const float* w_lin = (const float*)d_in[9];
    const float* b_lin = (const float*)d_in[10];

    cudaFuncSetAttribute(lstm2_kernel,
                         cudaFuncAttributeMaxDynamicSharedMemorySize, SMEM_BYTES);

    lstm2_kernel<<<GRID, NTH, SMEM_BYTES>>>(
        x, w_ih1, w_hh1, b_ih1, b_hh1,
        w_ih2, w_hh2, b_ih2, b_hh2,
        w_lin, b_lin, (float*)d_out);
}

// round 13
// speedup vs baseline: 1.5106x; 1.5106x over previous
#include <cuda_runtime.h>

// LSTM2: 2-layer LSTM, B=1024, T=1024, H=64, input dim 1, output 1/step.
// Persistent-RNN: 128 CTAs x 256 threads, 8 batch rows per CTA (R8 mapping).
// Thread = (unit n, k-quarter kq): all 4 gates x 8 rows x 16 k per matrix,
// f32x2 FMAs, 2-level kq butterfly -> lane kq finalizes rows {kq, kq+4}.
// SOFTWARE-PIPELINED PHASES (this round's change):
//   phase1: L1 dots -> bfly -> V*h2(p) dots (barrier-independent, hides the
//           shfl/epilogue latency) -> L1 epilogue -> store h1(q) -> bar1
//   phase2: U*h1(q) dots only -> +V partials -> bfly -> epilogue -> bar2 -> out
// V partials carried across bar1 in 32 registers.

namespace {

constexpr int T_LEN = 1024;
constexpr int RPC   = 8;             // batch rows per CTA
constexpr int NTH   = 256;           // threads per CTA
constexpr int GRID  = 1024 / RPC;    // 128

constexpr int WP    = 68;            // weight row pitch (floats)
constexpr int HP    = 72;            // h row pitch (floats)
constexpr int HB    = RPC * HP;      // 576 floats per h buffer

constexpr int SMEM_FLOATS = 3 * 256 * WP + 64 + 4 * HB + 16;
constexpr int SMEM_BYTES  = SMEM_FLOATS * 4;   // 218432 B

typedef unsigned long long u64;

__device__ __forceinline__ u64 fma2(u64 a, u64 b, u64 c) {
    u64 d;
    asm("fma.rn.f32x2 %0, %1, %2, %3;" : "=l"(d) : "l"(a), "l"(b), "l"(c));
    return d;
}
__device__ __forceinline__ float red2(u64 a) {
    return __uint_as_float((unsigned)a) + __uint_as_float((unsigned)(a >> 32));
}
__device__ __forceinline__ float tanh_f(float v) {
    float r;
    asm("tanh.approx.f32 %0, %1;" : "=f"(r) : "f"(v));
    return r;
}
__device__ __forceinline__ float sigm(float v) {
    return fmaf(tanh_f(0.5f * v), 0.5f, 0.5f);
}
__device__ __forceinline__ ulonglong2 ld2(const float* p) {
    return *(const ulonglong2*)p;
}

} // namespace

__global__ void __launch_bounds__(NTH, 1)
lstm2_kernel(const float* __restrict__ x,
             const float* __restrict__ w_ih1, const float* __restrict__ w_hh1,
             const float* __restrict__ b_ih1, const float* __restrict__ b_hh1,
             const float* __restrict__ w_ih2, const float* __restrict__ w_hh2,
             const float* __restrict__ b_ih2, const float* __restrict__ b_hh2,
             const float* __restrict__ w_lin, const float* __restrict__ b_lin,
             float* __restrict__ out)
{
    extern __shared__ float sm[];
    float* sWh1 = sm;                    // [256][68]
    float* sWi2 = sWh1 + 256 * WP;       // [256][68]
    float* sWh2 = sWi2 + 256 * WP;       // [256][68]
    float* sWl  = sWh2 + 256 * WP;       // [64]
    float* sH1  = sWl + 64;              // [2][8][72]
    float* sH2  = sH1 + 2 * HB;          // [2][8][72]
    float* sX   = sH2 + 2 * HB;          // [2][8]

    const int tid = threadIdx.x;
    const int rowbase = blockIdx.x * RPC;

    // ---- load weights into padded SMEM ----
    for (int i = tid; i < 256 * 64; i += NTH) {
        int j = i >> 6, k = i & 63;
        int off = j * WP + k;
        sWh1[off] = w_hh1[i];
        sWi2[off] = w_ih2[i];
        sWh2[off] = w_hh2[i];
    }
    if (tid < 64) sWl[tid] = w_lin[tid];
    for (int i = tid; i < 4 * HB; i += NTH) sH1[i] = 0.f;   // zeros h1 AND h2
    if (tid < RPC) sX[tid] = x[(rowbase + tid) * T_LEN];
    __syncthreads();

    // thread mapping: lane = kq*8 + nl; n = wid*8 + nl
    const int lid = tid & 31;
    const int wid = tid >> 5;
    const int kq  = lid >> 3;            // k-quarter 0..3
    const int n   = (wid << 3) | (lid & 7);
    const int kq16 = kq * 16;
    const int rA = kq, rB = kq + 4;      // rows this lane finalizes
    const int hi2 = kq & 2, hi1 = kq & 1;

    // per-thread constants from GMEM (once)
    const float b1i = b_ih1[n]       + b_hh1[n];
    const float b1f = b_ih1[n + 64]  + b_hh1[n + 64];
    const float b1g = b_ih1[n + 128] + b_hh1[n + 128];
    const float b1o = b_ih1[n + 192] + b_hh1[n + 192];
    const float b2i = b_ih2[n]       + b_hh2[n];
    const float b2f = b_ih2[n + 64]  + b_hh2[n + 64];
    const float b2g = b_ih2[n + 128] + b_hh2[n + 128];
    const float b2o = b_ih2[n + 192] + b_hh2[n + 192];
    const float wxi = w_ih1[n],       wxf = w_ih1[n + 64];
    const float wxg = w_ih1[n + 128], wxo = w_ih1[n + 192];
    const float blin = b_lin[0];

    // weight quarter base pointers
    const float* W1b = sWh1 + n * WP + kq16;    // layer1 w_hh (gate g at +g*64*WP)
    const float* Ub  = sWi2 + n * WP + kq16;    // layer2 w_ih
    const float* Vb  = sWh2 + n * WP + kq16;    // layer2 w_hh

    // persistent cell state (this lane's two rows)
    float c1a = 0.f, c1b = 0.f, c2a = 0.f, c2b = 0.f;

    for (int t = 0; t < T_LEN; ++t) {
        const int p = t & 1, q = p ^ 1;

        // prefetch next x (hidden under compute)
        float xn = 0.f;
        if (tid < RPC) {
            int tn = (t + 1 < T_LEN) ? (t + 1) : t;
            xn = x[(rowbase + tid) * T_LEN + tn];
        }

        // ================= PHASE 1 =================
        float vA1[4], vB1[4];      // layer-1 gate sums (rows rA, rB)
        float pr2[4][8];           // V*h2(p) partials, carried across bar1
        {
            // ---- L1 dots: W1 x h1(p) ----
            u64 acc[4][8] = {};
            {
                const float* hb = sH1 + p * HB + kq16;
                #pragma unroll
                for (int i = 0; i < 4; ++i) {
                    const int io = i * 4;
                    ulonglong2 wv0 = ld2(W1b + io);
                    ulonglong2 wv1 = ld2(W1b + 64 * WP + io);
                    ulonglong2 wv2 = ld2(W1b + 128 * WP + io);
                    ulonglong2 wv3 = ld2(W1b + 192 * WP + io);
                    #pragma unroll
                    for (int r = 0; r < 8; ++r) {
                        ulonglong2 hv = ld2(hb + r * HP + io);
                        acc[0][r] = fma2(wv0.x, hv.x, acc[0][r]);
                        acc[0][r] = fma2(wv0.y, hv.y, acc[0][r]);
                        acc[1][r] = fma2(wv1.x, hv.x, acc[1][r]);
                        acc[1][r] = fma2(wv1.y, hv.y, acc[1][r]);
                        acc[2][r] = fma2(wv2.x, hv.x, acc[2][r]);
                        acc[2][r] = fma2(wv2.y, hv.y, acc[2][r]);
                        acc[3][r] = fma2(wv3.x, hv.x, acc[3][r]);
                        acc[3][r] = fma2(wv3.y, hv.y, acc[3][r]);
                    }
                }
            }
            // ---- bfly for L1 (shfl chains overlap with V dots below) ----
            #pragma unroll
            for (int g = 0; g < 4; ++g) {
                float p0 = red2(acc[g][0]), p1 = red2(acc[g][1]);
                float p2 = red2(acc[g][2]), p3 = red2(acc[g][3]);
                float p4 = red2(acc[g][4]), p5 = red2(acc[g][5]);
                float p6 = red2(acc[g][6]), p7 = red2(acc[g][7]);
                float va0 = (hi2 ? p2 : p0) + __shfl_xor_sync(~0u, hi2 ? p0 : p2, 16);
                float va1 = (hi2 ? p3 : p1) + __shfl_xor_sync(~0u, hi2 ? p1 : p3, 16);
                float va4 = (hi2 ? p6 : p4) + __shfl_xor_sync(~0u, hi2 ? p4 : p6, 16);
                float va5 = (hi2 ? p7 : p5) + __shfl_xor_sync(~0u, hi2 ? p5 : p7, 16);
                vA1[g] = (hi1 ? va1 : va0) + __shfl_xor_sync(~0u, hi1 ? va0 : va1, 8);
                vB1[g] = (hi1 ? va5 : va4) + __shfl_xor_sync(~0u, hi1 ? va4 : va5, 8);
            }
            // ---- V dots: V x h2(p)  (no barrier dependency) ----
            u64 accv[4][8] = {};
            {
                const float* hb = sH2 + p * HB + kq16;
                #pragma unroll
                for (int i = 0; i < 4; ++i) {
                    const int io = i * 4;
                    ulonglong2 wv0 = ld2(Vb + io);
                    ulonglong2 wv1 = ld2(Vb + 64 * WP + io);
                    ulonglong2 wv2 = ld2(Vb + 128 * WP + io);
                    ulonglong2 wv3 = ld2(Vb + 192 * WP + io);
                    #pragma unroll
                    for (int r = 0; r < 8; ++r) {
                        ulonglong2 hv = ld2(hb + r * HP + io);
                        accv[0][r] = fma2(wv0.x, hv.x, accv[0][r]);
                        accv[0][r] = fma2(wv0.y, hv.y, accv[0][r]);
                        accv[1][r] = fma2(wv1.x, hv.x, accv[1][r]);
                        accv[1][r] = fma2(wv1.y, hv.y, accv[1][r]);
                        accv[2][r] = fma2(wv2.x, hv.x, accv[2][r]);
                        accv[2][r] = fma2(wv2.y, hv.y, accv[2][r]);
                        accv[3][r] = fma2(wv3.x, hv.x, accv[3][r]);
                        accv[3][r] = fma2(wv3.y, hv.y, accv[3][r]);
                    }
                }
            }
            #pragma unroll
            for (int g = 0; g < 4; ++g)
                #pragma unroll
                for (int r = 0; r < 8; ++r)
                    pr2[g][r] = red2(accv[g][r]);

            // ---- L1 epilogue (rows rA, rB) ----
            const float xsA = sX[p * RPC + rA];
            const float xsB = sX[p * RPC + rB];
            float ii = sigm(fmaf(wxi, xsA, b1i) + vA1[0]);
            float ff = sigm(fmaf(wxf, xsA, b1f) + vA1[1]);
            float gc = tanh_f(fmaf(wxg, xsA, b1g) + vA1[2]);
            float oo = sigm(fmaf(wxo, xsA, b1o) + vA1[3]);
            c1a = ff * c1a + ii * gc;
            sH1[q * HB + rA * HP + n] = oo * tanh_f(c1a);
            ii = sigm(fmaf(wxi, xsB, b1i) + vB1[0]);
            ff = sigm(fmaf(wxf, xsB, b1f) + vB1[1]);
            gc = tanh_f(fmaf(wxg, xsB, b1g) + vB1[2]);
            oo = sigm(fmaf(wxo, xsB, b1o) + vB1[3]);
            c1b = ff * c1b + ii * gc;
            sH1[q * HB + rB * HP + n] = oo * tanh_f(c1b);
        }
        if (tid < RPC) sX[q * RPC + tid] = xn;
        __syncthreads();   // bar1: h1(q) + x(q) published

        // ================= PHASE 2: U x h1(q) + V-partials =================
        {
            u64 acc[4][8] = {};
            {
                const float* hb = sH1 + q * HB + kq16;
                #pragma unroll
                for (int i = 0; i < 4; ++i) {
                    const int io = i * 4;
                    ulonglong2 wv0 = ld2(Ub + io);
                    ulonglong2 wv1 = ld2(Ub + 64 * WP + io);
                    ulonglong2 wv2 = ld2(Ub + 128 * WP + io);
                    ulonglong2 wv3 = ld2(Ub + 192 * WP + io);
                    #pragma unroll
                    for (int r = 0; r < 8; ++r) {
                        ulonglong2 hv = ld2(hb + r * HP + io);
                        acc[0][r] = fma2(wv0.x, hv.x, acc[0][r]);
                        acc[0][r] = fma2(wv0.y, hv.y, acc[0][r]);
                        acc[1][r] = fma2(wv1.x, hv.x, acc[1][r]);
                        acc[1][r] = fma2(wv1.y, hv.y, acc[1][r]);
                        acc[2][r] = fma2(wv2.x, hv.x, acc[2][r]);
                        acc[2][r] = fma2(wv2.y, hv.y, acc[2][r]);
                        acc[3][r] = fma2(wv3.x, hv.x, acc[3][r]);
                        acc[3][r] = fma2(wv3.y, hv.y, acc[3][r]);
                    }
                }
            }
            float vA[4], vB[4];
            #pragma unroll
            for (int g = 0; g < 4; ++g) {
                float p0 = red2(acc[g][0]) + pr2[g][0];
                float p1 = red2(acc[g][1]) + pr2[g][1];
                float p2 = red2(acc[g][2]) + pr2[g][2];
                float p3 = red2(acc[g][3]) + pr2[g][3];
                float p4 = red2(acc[g][4]) + pr2[g][4];
                float p5 = red2(acc[g][5]) + pr2[g][5];
                float p6 = red2(acc[g][6]) + pr2[g][6];
                float p7 = red2(acc[g][7]) + pr2[g][7];
                float va0 = (hi2 ? p2 : p0) + __shfl_xor_sync(~0u, hi2 ? p0 : p2, 16);
                float va1 = (hi2 ? p3 : p1) + __shfl_xor_sync(~0u, hi2 ? p1 : p3, 16);
                float va4 = (hi2 ? p6 : p4) + __shfl_xor_sync(~0u, hi2 ? p4 : p6, 16);
                float va5 = (hi2 ? p7 : p5) + __shfl_xor_sync(~0u, hi2 ? p5 : p7, 16);
                vA[g] = (hi1 ? va1 : va0) + __shfl_xor_sync(~0u, hi1 ? va0 : va1, 8);
                vB[g] = (hi1 ? va5 : va4) + __shfl_xor_sync(~0u, hi1 ? va4 : va5, 8);
            }
            float ii = sigm(b2i + vA[0]);
            float ff = sigm(b2f + vA[1]);
            float gc = tanh_f(b2g + vA[2]);
            float oo = sigm(b2o + vA[3]);
            c2a = ff * c2a + ii * gc;
            sH2[q * HB + rA * HP + n] = oo * tanh_f(c2a);
            ii = sigm(b2i + vB[0]);
            ff = sigm(b2f + vB[1]);
            gc = tanh_f(b2g + vB[2]);
            oo = sigm(b2o + vB[3]);
            c2b = ff * c2b + ii * gc;
            sH2[q * HB + rB * HP + n] = oo * tanh_f(c2b);
        }
        __syncthreads();   // bar2: h2(q) published

        // ====== output: warp w reduces row w of h2(q) against w_lin ======
        {
            const float* hr = sH2 + q * HB + wid * HP;
            float v = hr[lid] * sWl[lid] + hr[lid + 32] * sWl[lid + 32];
            #pragma unroll
            for (int off = 16; off; off >>= 1)
                v += __shfl_xor_sync(0xffffffffu, v, off);
            if (lid == 0) out[(rowbase + wid) * T_LEN + t] = v + blin;
        }
    }
}

extern "C" void kernel_launch(void* const* d_in, const int* in_sizes, int n_in,
                              void* d_out, int out_size)
{
    const float* x     = (const float*)d_in[0];
    const float* w_ih1 = (const float*)d_in[1];
    const float* w_hh1 = (const float*)d_in[2];
    const float* b_ih1 = (const float*)d_in[3];
    const float* b_hh1 = (const float*)d_in[4];
    const float* w_ih2 = (const float*)d_in[5];
    const float* w_hh2 = (const float*)d_in[6];
    const float* b_ih2 = (const float*)d_in[7];
    const float* b_hh2 = (const float*)d_in[8];
    const float* w_lin = (const float*)d_in[9];
    const float* b_lin = (const float*)d_in[10];

    cudaFuncSetAttribute(lstm2_kernel,
                         cudaFuncAttributeMaxDynamicSharedMemorySize, SMEM_BYTES);

    lstm2_kernel<<<GRID, NTH, SMEM_BYTES>>>(
        x, w_ih1, w_hh1, b_ih1, b_hh1,
        w_ih2, w_hh2, b_ih2, b_hh2,
        w_lin, b_lin, (float*)d_out);
}